// round 4
// baseline (speedup 1.0000x reference)
#include <cuda_runtime.h>
#include <cuda_bf16.h>
#include <cstdint>

#define N_NODES 100000
#define N_EDGES 1600000
#define NFEAT   256
#define NHID    128
#define NHID2   64

// -------- scratch (static device globals; no allocation at runtime) --------
__device__ float g_xw1[(size_t)N_NODES * NHID];   // x @ W1
__device__ float g_h  [(size_t)N_NODES * NHID];   // relu(spmm + b1)
__device__ float g_hw2[(size_t)N_NODES * NHID2];  // h @ W2
__device__ int   g_rowptr[N_NODES + 1];
__device__ int   g_is64;                          // 1 if edge indices are int64

// ---------------------------------------------------------------------------
// Detect index dtype. If edge_rows is int64 (values < 2^31 => high words 0),
// every odd 32-bit word is 0. If int32, the words near the end are sorted row
// ids ~99xxx (nonzero). Reads only within the first N_EDGES 32-bit words,
// which is in-bounds for both interpretations.
// ---------------------------------------------------------------------------
__global__ void detect_dtype_kernel(const int* __restrict__ rows_w32) {
    int all_zero = 1;
    for (int i = N_EDGES - 255; i < N_EDGES; i += 2)
        if (rows_w32[i] != 0) { all_zero = 0; break; }
    g_is64 = all_zero;
}

__device__ __forceinline__ int load_idx(const void* p, int i, int is64) {
    return is64 ? (int)((const long long*)p)[i] : ((const int*)p)[i];
}

// ---------------------------------------------------------------------------
// row_ptr from sorted COO rows: row_ptr[i] = lower_bound(rows, i)
// ---------------------------------------------------------------------------
__global__ void rowptr_kernel(const void* __restrict__ rows) {
    int i = blockIdx.x * blockDim.x + threadIdx.x;
    if (i > N_NODES) return;
    const int is64 = g_is64;
    int lo = 0, hi = N_EDGES;
    while (lo < hi) {
        int mid = (lo + hi) >> 1;
        if (load_idx(rows, mid, is64) < i) lo = mid + 1; else hi = mid;
    }
    g_rowptr[i] = lo;
}

// ---------------------------------------------------------------------------
// Register-blocked fp32 SGEMM: C[M,N] = A[M,K] @ B[K,N]
// (BM/TM)*(BN/TN) threads. N divisible by BN; M guarded.
// ---------------------------------------------------------------------------
template <int BM, int BN, int BK, int TM, int TN>
__global__ void sgemm_kernel(const float* __restrict__ A,
                             const float* __restrict__ B,
                             float* __restrict__ C,
                             int M, int N, int K) {
    constexpr int THREADS = (BM / TM) * (BN / TN);
    __shared__ float As[BK][BM];
    __shared__ float Bs[BK][BN];

    const int tid  = threadIdx.x;
    const int row0 = blockIdx.x * BM;
    const int col0 = blockIdx.y * BN;
    const int tx   = tid % (BN / TN);
    const int ty   = tid / (BN / TN);

    float acc[TM][TN];
#pragma unroll
    for (int i = 0; i < TM; i++)
#pragma unroll
        for (int j = 0; j < TN; j++) acc[i][j] = 0.f;

    for (int k0 = 0; k0 < K; k0 += BK) {
#pragma unroll
        for (int i = tid; i < BM * BK / 4; i += THREADS) {
            int r = i / (BK / 4);
            int c = (i % (BK / 4)) * 4;
            float4 v = make_float4(0.f, 0.f, 0.f, 0.f);
            if (row0 + r < M)
                v = *(const float4*)&A[(size_t)(row0 + r) * K + k0 + c];
            As[c + 0][r] = v.x;
            As[c + 1][r] = v.y;
            As[c + 2][r] = v.z;
            As[c + 3][r] = v.w;
        }
#pragma unroll
        for (int i = tid; i < BK * BN / 4; i += THREADS) {
            int r = i / (BN / 4);
            int c = (i % (BN / 4)) * 4;
            *(float4*)&Bs[r][c] =
                *(const float4*)&B[(size_t)(k0 + r) * N + col0 + c];
        }
        __syncthreads();

#pragma unroll
        for (int k = 0; k < BK; k++) {
            float a[TM], b[TN];
#pragma unroll
            for (int i = 0; i < TM; i++) a[i] = As[k][ty * TM + i];
#pragma unroll
            for (int j = 0; j < TN; j++) b[j] = Bs[k][tx * TN + j];
#pragma unroll
            for (int i = 0; i < TM; i++)
#pragma unroll
                for (int j = 0; j < TN; j++) acc[i][j] += a[i] * b[j];
        }
        __syncthreads();
    }

#pragma unroll
    for (int i = 0; i < TM; i++) {
        int r = row0 + ty * TM + i;
        if (r < M) {
#pragma unroll
            for (int j = 0; j < TN; j += 4) {
                *(float4*)&C[(size_t)r * N + col0 + tx * TN + j] =
                    make_float4(acc[i][j], acc[i][j + 1], acc[i][j + 2], acc[i][j + 3]);
            }
        }
    }
}

// ---------------------------------------------------------------------------
// CSR SpMM + bias + ReLU, warp-per-row.
//   out[row, f] = relu(bias[f] + sum_e vals[e] * dense[cols[e], f])
// Lane l owns features [VEC*l, VEC*l+VEC)  (VEC = F/32; float4/float2 loads ->
// fully coalesced gathers). Per-edge row offsets precomputed once per 32-edge
// chunk and broadcast via shfl. No block barriers -> no divergence hazard.
// ---------------------------------------------------------------------------
template <int F>
__global__ void spmm_bias_relu_kernel(const float* __restrict__ dense,
                                      const float* __restrict__ vals,
                                      const void*  __restrict__ cols,
                                      const float* __restrict__ bias,
                                      float* __restrict__ out) {
    constexpr int VEC   = F / 32;          // 4 (F=128) or 2 (F=64)
    constexpr int WARPS = 8;

    const int lane = threadIdx.x & 31;
    const int row  = blockIdx.x * WARPS + (threadIdx.x >> 5);
    if (row >= N_NODES) return;

    const int is64 = g_is64;
    const int s = g_rowptr[row];
    const int e = g_rowptr[row + 1];

    float acc[VEC];
#pragma unroll
    for (int k = 0; k < VEC; k++) acc[k] = 0.f;

    const float* dlane = dense + lane * VEC;   // this lane's feature slice

    for (int base = s; base < e; base += 32) {
        const int n = min(32, e - base);
        int   off = 0;                         // precomputed row offset (elems)
        float v   = 0.f;
        if (lane < n) {
            off = load_idx(cols, base + lane, is64) * F;
            v   = vals[base + lane];
        }
#pragma unroll 4
        for (int j = 0; j < n; j++) {
            const int   oj = __shfl_sync(0xffffffffu, off, j);
            const float vj = __shfl_sync(0xffffffffu, v,   j);
            if (VEC == 4) {
                float4 d = *(const float4*)(dlane + oj);
                acc[0] = fmaf(vj, d.x, acc[0]);
                acc[1] = fmaf(vj, d.y, acc[1]);
                acc[2] = fmaf(vj, d.z, acc[2]);
                acc[3] = fmaf(vj, d.w, acc[3]);
            } else {
                float2 d = *(const float2*)(dlane + oj);
                acc[0] = fmaf(vj, d.x, acc[0]);
                acc[1] = fmaf(vj, d.y, acc[1]);
            }
        }
    }

    float* op = &out[(size_t)row * F + lane * VEC];
    const float* bp = &bias[lane * VEC];
    if (VEC == 4) {
        float4 b = *(const float4*)bp;
        float4 r;
        r.x = fmaxf(acc[0] + b.x, 0.f);
        r.y = fmaxf(acc[1] + b.y, 0.f);
        r.z = fmaxf(acc[2] + b.z, 0.f);
        r.w = fmaxf(acc[3] + b.w, 0.f);
        *(float4*)op = r;
    } else {
        float2 b = *(const float2*)bp;
        float2 r;
        r.x = fmaxf(acc[0] + b.x, 0.f);
        r.y = fmaxf(acc[1] + b.y, 0.f);
        *(float2*)op = r;
    }
}

// ---------------------------------------------------------------------------
extern "C" void kernel_launch(void* const* d_in, const int* in_sizes, int n_in,
                              void* d_out, int out_size) {
    const float* x     = (const float*)d_in[0];
    const float* W1    = (const float*)d_in[1];
    const float* b1    = (const float*)d_in[2];
    const float* W2    = (const float*)d_in[3];
    const float* b2    = (const float*)d_in[4];
    const float* evals = (const float*)d_in[5];
    const void*  erows = d_in[6];
    const void*  ecols = d_in[7];
    float*       out   = (float*)d_out;

    float* xw1; cudaGetSymbolAddress((void**)&xw1, g_xw1);
    float* h;   cudaGetSymbolAddress((void**)&h,   g_h);
    float* hw2; cudaGetSymbolAddress((void**)&hw2, g_hw2);

    // 0) detect int32 vs int64 edge indices
    detect_dtype_kernel<<<1, 1>>>((const int*)erows);

    // 1) row_ptr (binary search per row over sorted rows)
    rowptr_kernel<<<(N_NODES + 256) / 256, 256>>>(erows);

    // 2) GEMM1: xw1 = x @ W1   (M=100000, N=128, K=256)
    {
        constexpr int BM = 128, BN = 128, BK = 8, TM = 8, TN = 8;
        dim3 grid((N_NODES + BM - 1) / BM, NHID / BN);
        sgemm_kernel<BM, BN, BK, TM, TN>
            <<<grid, (BM / TM) * (BN / TN)>>>(x, W1, xw1, N_NODES, NHID, NFEAT);
    }

    // 3) SpMM1 + b1 + ReLU: h   (F=128, warp-per-row)
    spmm_bias_relu_kernel<NHID>
        <<<(N_NODES + 7) / 8, 256>>>(xw1, evals, ecols, b1, h);

    // 4) GEMM2: hw2 = h @ W2   (M=100000, N=64, K=128)
    {
        constexpr int BM = 128, BN = 64, BK = 8, TM = 8, TN = 4;
        dim3 grid((N_NODES + BM - 1) / BM, NHID2 / BN);
        sgemm_kernel<BM, BN, BK, TM, TN>
            <<<grid, (BM / TM) * (BN / TN)>>>(h, W2, hw2, N_NODES, NHID2, NHID);
    }

    // 5) SpMM2 + b2 + ReLU: out   (F=64, warp-per-row)
    spmm_bias_relu_kernel<NHID2>
        <<<(N_NODES + 7) / 8, 256>>>(hw2, evals, ecols, b2, out);
}

// round 6
// speedup vs baseline: 1.2681x; 1.2681x over previous
#include <cuda_runtime.h>
#include <cuda_bf16.h>
#include <cstdint>

#define N_NODES 100000
#define N_EDGES 1600000
#define NFEAT   256
#define NHID    128
#define NHID2   64

// ===========================================================================
// helpers
// ===========================================================================
__device__ __forceinline__ uint32_t smem_u32(const void* p) {
    uint32_t a;
    asm("{ .reg .u64 t; cvta.to.shared.u64 t, %1; cvt.u32.u64 %0, t; }"
        : "=r"(a) : "l"(p));
    return a;
}
__device__ __host__ __forceinline__ uint32_t sw128(uint32_t off) {
    return off ^ ((off >> 3) & 0x70);
}
#define LDSM_X4(r0, r1, r2, r3, addr) \
    asm volatile("ldmatrix.sync.aligned.m8n8.x4.shared.b16 {%0,%1,%2,%3}, [%4];" \
                 : "=r"(r0), "=r"(r1), "=r"(r2), "=r"(r3) : "r"(addr))
#define MMA_BF16(d, a, b) \
    asm volatile("mma.sync.aligned.m16n8k16.row.col.f32.bf16.bf16.f32 " \
                 "{%0,%1,%2,%3}, {%4,%5,%6,%7}, {%8,%9}, {%0,%1,%2,%3};" \
                 : "+f"((d)[0]), "+f"((d)[1]), "+f"((d)[2]), "+f"((d)[3]) \
                 : "r"((a)[0]), "r"((a)[1]), "r"((a)[2]), "r"((a)[3]), \
                   "r"((b)[0]), "r"((b)[1]))

// ===========================================================================
// scratch (static device globals; no runtime allocation)
// ===========================================================================
__device__ float g_xw1[(size_t)N_NODES * NHID];
__device__ float g_h  [(size_t)N_NODES * NHID];
__device__ float g_hw2[(size_t)N_NODES * NHID2];
__device__ int   g_rowptr[N_NODES + 1];
__device__ int   g_is64;

// pre-transposed, pre-swizzled, hi/lo-split weight chunk images:
// per 64-k chunk: [NDIM rows x 64 k] bf16, row pitch 128B, SW128 swizzle.
__device__ __align__(16) uint8_t g_W1hi[4 * 16384];
__device__ __align__(16) uint8_t g_W1lo[4 * 16384];
__device__ __align__(16) uint8_t g_W2hi[2 * 8192];
__device__ __align__(16) uint8_t g_W2lo[2 * 8192];

// ===========================================================================
// dtype detect + rowptr (unchanged; validated in the 384us pass)
// ===========================================================================
__global__ void detect_dtype_kernel(const int* __restrict__ rows_w32) {
    int all_zero = 1;
    for (int i = N_EDGES - 255; i < N_EDGES; i += 2)
        if (rows_w32[i] != 0) { all_zero = 0; break; }
    g_is64 = all_zero;
}
__device__ __forceinline__ int load_idx(const void* p, int i, int is64) {
    return is64 ? (int)((const long long*)p)[i] : ((const int*)p)[i];
}
__global__ void rowptr_kernel(const void* __restrict__ rows) {
    int i = blockIdx.x * blockDim.x + threadIdx.x;
    if (i > N_NODES) return;
    const int is64 = g_is64;
    int lo = 0, hi = N_EDGES;
    while (lo < hi) {
        int mid = (lo + hi) >> 1;
        if (load_idx(rows, mid, is64) < i) lo = mid + 1; else hi = mid;
    }
    g_rowptr[i] = lo;
}

// ===========================================================================
// weight prep: W[K,N] -> per-chunk [N x 64k] bf16 hi/lo swizzled images
// ===========================================================================
__global__ void prep_weights_kernel(const float* __restrict__ W1,
                                    const float* __restrict__ W2) {
    const int tid = blockIdx.x * blockDim.x + threadIdx.x;
    const int nthreads = gridDim.x * blockDim.x;
    for (int idx = tid; idx < NFEAT * NHID; idx += nthreads) {
        int k = idx / NHID, n = idx % NHID;
        float w = W1[idx];
        __nv_bfloat16 hi = __float2bfloat16(w);
        __nv_bfloat16 lo = __float2bfloat16(w - __bfloat162float(hi));
        int chunk = k >> 6, kl = k & 63;
        uint32_t off = sw128((uint32_t)(n * 128 + kl * 2));
        *(__nv_bfloat16*)(g_W1hi + chunk * 16384 + off) = hi;
        *(__nv_bfloat16*)(g_W1lo + chunk * 16384 + off) = lo;
    }
    for (int idx = tid; idx < NHID * NHID2; idx += nthreads) {
        int k = idx / NHID2, n = idx % NHID2;
        float w = W2[idx];
        __nv_bfloat16 hi = __float2bfloat16(w);
        __nv_bfloat16 lo = __float2bfloat16(w - __bfloat162float(hi));
        int chunk = k >> 6, kl = k & 63;
        uint32_t off = sw128((uint32_t)(n * 128 + kl * 2));
        *(__nv_bfloat16*)(g_W2hi + chunk * 8192 + off) = hi;
        *(__nv_bfloat16*)(g_W2lo + chunk * 8192 + off) = lo;
    }
}

// ===========================================================================
// HMMA (mma.sync) GEMM:  C[M,NDIM] = A[M,KDIM] @ W[KDIM,NDIM], fp32 in/out.
// 3-product bf16 hi/lo split, fp32 accumulators.
// 128-row tile / CTA, 256 threads = 8 warps (4 m-warps x 2 n-warps).
// Warp tile 32m x NDIM/2 n. K chunked by 64 (128B SW128 smem rows).
// ===========================================================================
template <int NDIM, int KDIM>
__global__ void mma_gemm_kernel(const float* __restrict__ A,
                                const uint8_t* __restrict__ Bhi,
                                const uint8_t* __restrict__ Blo,
                                float* __restrict__ C, int M) {
    constexpr int NCHUNK = KDIM / 64;
    constexpr int BT     = NDIM * 128;   // B chunk bytes
    constexpr int NT8    = NDIM / 16;    // n8 tiles per warp (warp spans NDIM/2)
    constexpr int SM_AHI = 0;
    constexpr int SM_ALO = 16384;
    constexpr int SM_BHI = 32768;
    constexpr int SM_BLO = 32768 + BT;

    extern __shared__ __align__(1024) char smem[];
    const uint32_t sb = smem_u32(smem);

    const int tid  = threadIdx.x;
    const int wid  = tid >> 5;
    const int lane = tid & 31;
    const int m0   = (wid & 3) * 32;          // warp row base within tile
    const int n0   = (wid >> 2) * (NDIM / 2); // warp col base
    const int row0 = blockIdx.x * 128;

    float acc[2][NT8][4];
#pragma unroll
    for (int mi = 0; mi < 2; mi++)
#pragma unroll
        for (int ni = 0; ni < NT8; ni++)
#pragma unroll
            for (int j = 0; j < 4; j++) acc[mi][ni][j] = 0.f;

    // precompute ldmatrix lane-address components
    const int a_row  = lane & 15;                       // 0..15
    const int a_colb = ((lane >> 4) << 3) * 2;          // 0 or 16 bytes
    const int b_row  = (lane & 7) + ((lane >> 4) << 3); // 0..15
    const int b_colb = (lane & 8) * 2;                  // 0 or 16 bytes

    for (int ch = 0; ch < NCHUNK; ch++) {
        const int k0g = ch * 64;
        // ---- stage A: fp32 -> bf16 hi/lo, swizzled ----
#pragma unroll 2
        for (int i = tid; i < 2048; i += 256) {
            int r  = i >> 4;
            int c4 = i & 15;
            float4 v = make_float4(0.f, 0.f, 0.f, 0.f);
            if (row0 + r < M)
                v = *(const float4*)&A[(size_t)(row0 + r) * KDIM + k0g + c4 * 4];
            __nv_bfloat16 hx = __float2bfloat16(v.x);
            __nv_bfloat16 hy = __float2bfloat16(v.y);
            __nv_bfloat16 hz = __float2bfloat16(v.z);
            __nv_bfloat16 hw = __float2bfloat16(v.w);
            __nv_bfloat162 h01; h01.x = hx; h01.y = hy;
            __nv_bfloat162 h23; h23.x = hz; h23.y = hw;
            __nv_bfloat162 l01, l23;
            l01.x = __float2bfloat16(v.x - __bfloat162float(hx));
            l01.y = __float2bfloat16(v.y - __bfloat162float(hy));
            l23.x = __float2bfloat16(v.z - __bfloat162float(hz));
            l23.y = __float2bfloat16(v.w - __bfloat162float(hw));
            uint32_t off = sw128((uint32_t)(r * 128 + c4 * 8));
            uint2 uh, ul;
            uh.x = *(uint32_t*)&h01; uh.y = *(uint32_t*)&h23;
            ul.x = *(uint32_t*)&l01; ul.y = *(uint32_t*)&l23;
            *(uint2*)(smem + SM_AHI + off) = uh;
            *(uint2*)(smem + SM_ALO + off) = ul;
        }
        // ---- copy pre-swizzled B chunk images ----
        {
            const float4* shi = (const float4*)(Bhi + ch * BT);
            const float4* slo = (const float4*)(Blo + ch * BT);
            float4* dhi = (float4*)(smem + SM_BHI);
            float4* dlo = (float4*)(smem + SM_BLO);
#pragma unroll 2
            for (int i = tid; i < BT / 16; i += 256) {
                dhi[i] = shi[i];
                dlo[i] = slo[i];
            }
        }
        __syncthreads();

        // ---- compute: 4 k16 steps ----
#pragma unroll
        for (int ks = 0; ks < 4; ks++) {
            const int kb = ks * 32;   // byte offset of k0 within 128B row
            uint32_t ahi[2][4], alo[2][4];
#pragma unroll
            for (int mi = 0; mi < 2; mi++) {
                uint32_t off = sw128((uint32_t)((m0 + mi * 16 + a_row) * 128
                                                + kb + a_colb));
                LDSM_X4(ahi[mi][0], ahi[mi][1], ahi[mi][2], ahi[mi][3],
                        sb + SM_AHI + off);
                LDSM_X4(alo[mi][0], alo[mi][1], alo[mi][2], alo[mi][3],
                        sb + SM_ALO + off);
            }
#pragma unroll
            for (int np = 0; np < NT8 / 2; np++) {
                uint32_t off = sw128((uint32_t)((n0 + np * 16 + b_row) * 128
                                                + kb + b_colb));
                uint32_t bhi[4], blo[4];
                LDSM_X4(bhi[0], bhi[1], bhi[2], bhi[3], sb + SM_BHI + off);
                LDSM_X4(blo[0], blo[1], blo[2], blo[3], sb + SM_BLO + off);
#pragma unroll
                for (int mi = 0; mi < 2; mi++) {
                    MMA_BF16(acc[mi][np * 2],     ahi[mi], &bhi[0]);
                    MMA_BF16(acc[mi][np * 2],     ahi[mi], &blo[0]);
                    MMA_BF16(acc[mi][np * 2],     alo[mi], &bhi[0]);
                    MMA_BF16(acc[mi][np * 2 + 1], ahi[mi], &bhi[2]);
                    MMA_BF16(acc[mi][np * 2 + 1], ahi[mi], &blo[2]);
                    MMA_BF16(acc[mi][np * 2 + 1], alo[mi], &bhi[2]);
                }
            }
        }
        __syncthreads();
    }

    // ---- epilogue: fragment -> gmem (d0,d1 / d2,d3 are col-adjacent pairs) --
#pragma unroll
    for (int mi = 0; mi < 2; mi++) {
        const int r1 = row0 + m0 + mi * 16 + (lane >> 2);
        const int r2 = r1 + 8;
#pragma unroll
        for (int ni = 0; ni < NT8; ni++) {
            const int col = n0 + ni * 8 + 2 * (lane & 3);
            if (r1 < M) {
                float2 v; v.x = acc[mi][ni][0]; v.y = acc[mi][ni][1];
                *(float2*)&C[(size_t)r1 * NDIM + col] = v;
            }
            if (r2 < M) {
                float2 v; v.x = acc[mi][ni][2]; v.y = acc[mi][ni][3];
                *(float2*)&C[(size_t)r2 * NDIM + col] = v;
            }
        }
    }
}

// ===========================================================================
// CSR SpMM + bias + ReLU, warp-per-row (unchanged: measured at its L2 floor)
// ===========================================================================
template <int F>
__global__ void spmm_bias_relu_kernel(const float* __restrict__ dense,
                                      const float* __restrict__ vals,
                                      const void*  __restrict__ cols,
                                      const float* __restrict__ bias,
                                      float* __restrict__ out) {
    constexpr int VEC   = F / 32;
    constexpr int WARPS = 8;

    const int lane = threadIdx.x & 31;
    const int row  = blockIdx.x * WARPS + (threadIdx.x >> 5);
    if (row >= N_NODES) return;

    const int is64 = g_is64;
    const int s = g_rowptr[row];
    const int e = g_rowptr[row + 1];

    float acc[VEC];
#pragma unroll
    for (int k = 0; k < VEC; k++) acc[k] = 0.f;

    const float* dlane = dense + lane * VEC;

    for (int base = s; base < e; base += 32) {
        const int n = min(32, e - base);
        int   off = 0;
        float v   = 0.f;
        if (lane < n) {
            off = load_idx(cols, base + lane, is64) * F;
            v   = vals[base + lane];
        }
#pragma unroll 4
        for (int j = 0; j < n; j++) {
            const int   oj = __shfl_sync(0xffffffffu, off, j);
            const float vj = __shfl_sync(0xffffffffu, v,   j);
            if (VEC == 4) {
                float4 d = *(const float4*)(dlane + oj);
                acc[0] = fmaf(vj, d.x, acc[0]);
                acc[1] = fmaf(vj, d.y, acc[1]);
                acc[2] = fmaf(vj, d.z, acc[2]);
                acc[3] = fmaf(vj, d.w, acc[3]);
            } else {
                float2 d = *(const float2*)(dlane + oj);
                acc[0] = fmaf(vj, d.x, acc[0]);
                acc[1] = fmaf(vj, d.y, acc[1]);
            }
        }
    }

    float* op = &out[(size_t)row * F + lane * VEC];
    const float* bp = &bias[lane * VEC];
    if (VEC == 4) {
        float4 b = *(const float4*)bp;
        float4 r;
        r.x = fmaxf(acc[0] + b.x, 0.f);
        r.y = fmaxf(acc[1] + b.y, 0.f);
        r.z = fmaxf(acc[2] + b.z, 0.f);
        r.w = fmaxf(acc[3] + b.w, 0.f);
        *(float4*)op = r;
    } else {
        float2 b = *(const float2*)bp;
        float2 r;
        r.x = fmaxf(acc[0] + b.x, 0.f);
        r.y = fmaxf(acc[1] + b.y, 0.f);
        *(float2*)op = r;
    }
}

// ===========================================================================
extern "C" void kernel_launch(void* const* d_in, const int* in_sizes, int n_in,
                              void* d_out, int out_size) {
    const float* x     = (const float*)d_in[0];
    const float* W1    = (const float*)d_in[1];
    const float* b1    = (const float*)d_in[2];
    const float* W2    = (const float*)d_in[3];
    const float* b2    = (const float*)d_in[4];
    const float* evals = (const float*)d_in[5];
    const void*  erows = d_in[6];
    const void*  ecols = d_in[7];
    float*       out   = (float*)d_out;

    float* xw1; cudaGetSymbolAddress((void**)&xw1, g_xw1);
    float* h;   cudaGetSymbolAddress((void**)&h,   g_h);
    float* hw2; cudaGetSymbolAddress((void**)&hw2, g_hw2);
    uint8_t *w1hi, *w1lo, *w2hi, *w2lo;
    cudaGetSymbolAddress((void**)&w1hi, g_W1hi);
    cudaGetSymbolAddress((void**)&w1lo, g_W1lo);
    cudaGetSymbolAddress((void**)&w2hi, g_W2hi);
    cudaGetSymbolAddress((void**)&w2lo, g_W2lo);

    constexpr int SMEM1 = 32768 + 2 * (NHID  * 128);  // 65536
    constexpr int SMEM2 = 32768 + 2 * (NHID2 * 128);  // 49152
    cudaFuncSetAttribute(mma_gemm_kernel<NHID, NFEAT>,
                         cudaFuncAttributeMaxDynamicSharedMemorySize, SMEM1);
    cudaFuncSetAttribute(mma_gemm_kernel<NHID2, NHID>,
                         cudaFuncAttributeMaxDynamicSharedMemorySize, SMEM2);

    // 0) dtype detect + rowptr + weight prep
    detect_dtype_kernel<<<1, 1>>>((const int*)erows);
    rowptr_kernel<<<(N_NODES + 256) / 256, 256>>>(erows);
    prep_weights_kernel<<<64, 256>>>(W1, W2);

    const int ntiles = (N_NODES + 127) / 128;   // 782

    // 1) GEMM1: xw1 = x @ W1  (HMMA, 3-product bf16 split)
    mma_gemm_kernel<NHID, NFEAT><<<ntiles, 256, SMEM1>>>(x, w1hi, w1lo, xw1, N_NODES);

    // 2) SpMM1 + b1 + ReLU
    spmm_bias_relu_kernel<NHID>
        <<<(N_NODES + 7) / 8, 256>>>(xw1, evals, ecols, b1, h);

    // 3) GEMM2: hw2 = h @ W2
    mma_gemm_kernel<NHID2, NHID><<<ntiles, 256, SMEM2>>>(h, w2hi, w2lo, hw2, N_NODES);

    // 4) SpMM2 + b2 + ReLU
    spmm_bias_relu_kernel<NHID2>
        <<<(N_NODES + 7) / 8, 256>>>(hw2, evals, ecols, b2, out);
}